// round 6
// baseline (speedup 1.0000x reference)
#include <cuda_runtime.h>

// out[t][l][d]: l==0 -> inputs[t][d], else memory[l][d]
// T=2048, L=64, D=1024 fp32. Pure store-bandwidth kernel (512 MiB writes,
// measured wall-clock ~7.3 TB/s = ~91% of HBM spec -> near roofline).
//
// R2 winning inner body (U=8 rows per iteration, float4, __ldg + __stcs),
// now persistent: grid = SMs * occ blocks, grid-stride loop over row-groups.
// No wave transitions, no tail imbalance, SMs stream continuously.

static constexpr int T = 2048;
static constexpr int L = 64;
static constexpr int D4 = 1024 / 4;            // 256 float4 per row
static constexpr int ROWS = T * L;             // 131072
static constexpr int U = 8;                    // rows per iteration
static constexpr int GROUPS = ROWS / U;        // 16384 row-groups

__global__ __launch_bounds__(256, 8)
void sliding_window_memory_kernel(const float4* __restrict__ in,
                                  const float4* __restrict__ mem,
                                  float4* __restrict__ out)
{
    const int tid = threadIdx.x;

    for (int g = blockIdx.x; g < GROUPS; g += gridDim.x) {
        const int row0 = g * U;
        float4* __restrict__ o = out + (long)row0 * D4 + tid;

        float4 v[U];
#pragma unroll
        for (int u = 0; u < U; ++u) {
            const int row = row0 + u;
            const int l = row & (L - 1);
            const int t = row >> 6;
            const float4* __restrict__ s =
                (l == 0) ? (in + t * D4 + tid) : (mem + l * D4 + tid);
            v[u] = __ldg(s);               // in: DRAM once; tail: L2-resident
        }
#pragma unroll
        for (int u = 0; u < U; ++u) {
            __stcs(o + u * D4, v[u]);      // streaming store
        }
    }
}

extern "C" void kernel_launch(void* const* d_in, const int* in_sizes, int n_in,
                              void* d_out, int out_size)
{
    const float4* in  = (const float4*)d_in[0];   // inputs [T, D] fp32
    const float4* mem = (const float4*)d_in[1];   // memory [L, D] fp32
    float4* out = (float4*)d_out;                 // [T, L, D] fp32

    const int threads = 256;
    const int blocks = 152 * 8;                   // persistent: SMs * occ
    sliding_window_memory_kernel<<<blocks, threads>>>(in, mem, out);
}

// round 7
// speedup vs baseline: 1.1645x; 1.1645x over previous
#include <cuda_runtime.h>

// out[t][l][d]: l==0 -> inputs[t][d], else memory[l][d]
// T=2048, L=64, D=1024 fp32. Pure store-bandwidth kernel (512 MiB writes,
// ~91% of HBM spec achieved). R2 inner body (float4, __ldg + __stcs), with
// wave-quantization fix: grid = 13 * 1216 = 15808 blocks (exactly 13 full
// waves at 152 SMs x 8 blocks). First HEAVY blocks take 9 rows, rest 8.

static constexpr int T = 2048;
static constexpr int L = 64;
static constexpr int D4 = 1024 / 4;              // 256 float4 per row
static constexpr int ROWS = T * L;               // 131072
static constexpr int CONC = 152 * 8;             // concurrent blocks (GB300)
static constexpr int WAVES = 13;
static constexpr int GRID = CONC * WAVES;        // 15808
static constexpr int HEAVY = ROWS - GRID * 8;    // 4608 blocks with 9 rows

__device__ __forceinline__ const float4* src_ptr(int row, int tid,
                                                 const float4* __restrict__ in,
                                                 const float4* __restrict__ mem)
{
    const int l = row & (L - 1);
    const int t = row >> 6;
    return (l == 0) ? (in + t * D4 + tid) : (mem + l * D4 + tid);
}

__global__ __launch_bounds__(256, 8)
void sliding_window_memory_kernel(const float4* __restrict__ in,
                                  const float4* __restrict__ mem,
                                  float4* __restrict__ out)
{
    const int tid = threadIdx.x;
    const int bid = blockIdx.x;
    const bool heavy = bid < HEAVY;
    const int row0 = bid * 8 + (heavy ? bid : HEAVY);

    float4* __restrict__ o = out + (long)row0 * D4 + tid;

    // main batch: 8 rows, loads batched for MLP, then stores
    float4 v[8];
#pragma unroll
    for (int u = 0; u < 8; ++u)
        v[u] = __ldg(src_ptr(row0 + u, tid, in, mem));
#pragma unroll
    for (int u = 0; u < 8; ++u)
        __stcs(o + u * D4, v[u]);

    // optional 9th row for heavy blocks (keeps live regs at 8 x float4)
    if (heavy) {
        float4 w = __ldg(src_ptr(row0 + 8, tid, in, mem));
        __stcs(o + 8 * D4, w);
    }
}

extern "C" void kernel_launch(void* const* d_in, const int* in_sizes, int n_in,
                              void* d_out, int out_size)
{
    const float4* in  = (const float4*)d_in[0];   // inputs [T, D] fp32
    const float4* mem = (const float4*)d_in[1];   // memory [L, D] fp32
    float4* out = (float4*)d_out;                 // [T, L, D] fp32

    sliding_window_memory_kernel<<<GRID, 256>>>(in, mem, out);
}